// round 6
// baseline (speedup 1.0000x reference)
#include <cuda_runtime.h>

// ButterflyRotationLayer: R = B(d,d) @ B(d,d/2) @ ... @ B(d,2), d=4096, 12 stages.
//
// Split at k=64:
//   H = stages k=4096..128 : H[r,l] != 0 only when l == r (mod 64).
//       For fixed r6 = r&63, the 64 rows {r6+64*rh} share ONE 64x64 m-space
//       butterfly matrix Hhat_{r6}[rh, m].
//   T = stages k=64..2     : block-diagonal, 64 independent 64x64 matrices That_B.
// Exactly one l contributes per output element:
//   R[r6+64*rh, 64*B+cc] = Hhat_{r6}[rh, B] * That_B[r6, cc]
//
// Kernel 1 (128 blocks): builds all 128 small 64x64 matrices, sincos once per
//   theta (24.6K total instead of 786K).
// Kernel 2 (16384 blocks): massive-grid outer product, 1 float4/thread,
//   direct L2 reads (L1-broadcast friendly), fully coalesced stores.
//   (Few-block SMEM-staged variants measured 2.7x SLOWER: exposed STG issue
//   cost + barrier serialization + low occupancy.)

#define D 4096

// g_H[r*64 + m]  = Hhat_{r&63}[r>>6, m]
__device__ __align__(16) float g_H[D * 64];
// g_T[(B*64+rr)*64 + cc] = That_B[rr, cc]
__device__ __align__(16) float g_T[D * 64];

// ---------------------------------------------------------------------------
// Kernel 1: block b<64 -> head matrix Hhat_{r6=b}; b>=64 -> tail matrix That_{b-64}.
// M = I; each stage applies column Givens rotations (M <- M @ B_i).
// ---------------------------------------------------------------------------
__global__ __launch_bounds__(256) void butterfly_mats_kernel(const float* __restrict__ thetas) {
    __shared__ float sm[64][65];
    __shared__ float cs_c[32], cs_s[32];

    const int tid      = threadIdx.x;
    const int b        = blockIdx.x;
    const bool is_head = (b < 64);

#pragma unroll
    for (int k = 0; k < 16; ++k) {
        const int e = tid + k * 256;
        sm[e >> 6][e & 63] = ((e >> 6) == (e & 63)) ? 1.0f : 0.0f;
    }
    __syncthreads();

    const int j = tid & 31;

#pragma unroll
    for (int ii = 0; ii < 6; ++ii) {
        const int half  = 32 >> ii;
        const int bm    = j >> (5 - ii);
        const int jm    = j & (half - 1);
        const int p_loc = (bm << (6 - ii)) + jm;
        const int q_loc = p_loc + half;

        if (tid < 32) {
            int theta_idx;
            if (is_head) {
                const int p    = b + (p_loc << 6);
                const int logk = 12 - ii;
                const int hh   = 2048 >> ii;
                theta_idx = ii * 2048 + (p >> logk) * hh + (p & ((1 << logk) - 1));
            } else {
                const int p    = ((b - 64) << 6) + p_loc;
                const int logk = 6 - ii;
                const int hh   = 32 >> ii;
                theta_idx = (ii + 6) * 2048 + (p >> logk) * hh + (p & ((1 << logk) - 1));
            }
            float s, c;
            sincosf(thetas[theta_idx], &s, &c);
            cs_c[tid] = c;
            cs_s[tid] = s;
        }
        __syncthreads();

        const float c = cs_c[j];
        const float s = cs_s[j];
#pragma unroll
        for (int k = 0; k < 8; ++k) {
            const int row = (tid >> 5) + (k << 3);
            const float a  = sm[row][p_loc];
            const float bb = sm[row][q_loc];
            sm[row][p_loc] = c * a + s * bb;
            sm[row][q_loc] = c * bb - s * a;
        }
        __syncthreads();
    }

    if (is_head) {
#pragma unroll
        for (int k = 0; k < 16; ++k) {
            const int e  = tid + k * 256;
            const int rh = e >> 6;
            const int m  = e & 63;
            g_H[(b << 6) + (rh << 12) + m] = sm[rh][m];
        }
    } else {
        const int base = (b - 64) << 12;
#pragma unroll
        for (int k = 0; k < 16; ++k) {
            const int e = tid + k * 256;
            g_T[base + e] = sm[e >> 6][e & 63];
        }
    }
}

// ---------------------------------------------------------------------------
// Kernel 2: R[r,c] = g_H[r*64 + (c>>6)] * g_T[((c>>6)*64 + (r&63))*64 + (c&63)]
// One float4 per thread, 16384 independent blocks. Per warp: H is a 2-value
// broadcast, T reads are 2 coalesced 256B regions, store is one 4KB coalesced
// STG.128 burst. No SMEM, no barriers.
// ---------------------------------------------------------------------------
__global__ __launch_bounds__(256) void outer_product_kernel(float4* __restrict__ out) {
    const int idx = blockIdx.x * blockDim.x + threadIdx.x;  // 0 .. 4M-1
    const int r   = idx >> 10;          // row (1024 float4 per row)
    const int c4  = idx & 1023;
    const int c   = c4 << 2;
    const int B   = c >> 6;

    const float  h = g_H[(r << 6) + B];
    const int    l = (B << 6) + (r & 63);
    const float4 t = *reinterpret_cast<const float4*>(&g_T[(l << 6) + (c & 63)]);

    out[idx] = make_float4(h * t.x, h * t.y, h * t.z, h * t.w);
}

extern "C" void kernel_launch(void* const* d_in, const int* in_sizes, int n_in,
                              void* d_out, int out_size) {
    const float* thetas = (const float*)d_in[0];  // [12, 2048] fp32
    float4* out = (float4*)d_out;                 // [4096, 4096] fp32

    butterfly_mats_kernel<<<128, 256>>>(thetas);
    outer_product_kernel<<<(D * (D / 4)) / 256, 256>>>(out);
}

// round 7
// speedup vs baseline: 1.2230x; 1.2230x over previous
#include <cuda_runtime.h>

// ButterflyRotationLayer: R = B(d,d) @ B(d,d/2) @ ... @ B(d,2), d=4096, 12 stages.
//
// Split at k=64:
//   H = stages k=4096..128 : H[r,l] != 0 only when l == r (mod 64).
//       For fixed r6 = r&63, the 64 rows {r6+64*rh} share ONE 64x64 m-space
//       butterfly matrix Hhat_{r6}[rh, m].
//   T = stages k=64..2     : block-diagonal, 64 independent 64x64 matrices That_B.
// Exactly one l contributes per output element:
//   R[r6+64*rh, 64*B+cc] = Hhat_{r6}[rh, B] * That_B[r6, cc]
//
// Kernel 1 (128 blocks): builds all 128 small 64x64 matrices; ALL 192 sincos
//   per block computed in parallel upfront (no per-stage serialization).
// Kernel 2 (2048 blocks): each thread loads its t-float4 ONCE and emits 8
//   output rows (r6 fixed, rh varying) -> ~7 instrs per float4 instead of ~20.
//   (Previous 1-float4/thread versions were instruction-issue-bound at ~16us.)

#define D 4096

// g_H[r*64 + m]  = Hhat_{r&63}[r>>6, m]
__device__ __align__(16) float g_H[D * 64];
// g_T[(B*64+rr)*64 + cc] = That_B[rr, cc]
__device__ __align__(16) float g_T[D * 64];

// ---------------------------------------------------------------------------
// Kernel 1: block b<64 -> head matrix Hhat_{r6=b}; b>=64 -> tail matrix That_{b-64}.
// M = I; each stage applies column Givens rotations (M <- M @ B_i).
// All (c,s) pairs are theta-only -> computed in parallel before the stage loop.
// ---------------------------------------------------------------------------
__global__ __launch_bounds__(256) void butterfly_mats_kernel(const float* __restrict__ thetas) {
    __shared__ float sm[64][65];
    __shared__ float cs_c[6][32], cs_s[6][32];

    const int tid      = threadIdx.x;
    const int b        = blockIdx.x;
    const bool is_head = (b < 64);

    // 192 parallel sincos: thread tid -> (stage ii = tid>>5, pair j = tid&31)
    if (tid < 192) {
        const int ii   = tid >> 5;
        const int j    = tid & 31;
        const int half = 32 >> ii;
        const int bm   = j >> (5 - ii);
        const int jm   = j & (half - 1);
        const int p_loc = (bm << (6 - ii)) + jm;
        int theta_idx;
        if (is_head) {
            const int p    = b + (p_loc << 6);
            const int logk = 12 - ii;
            const int hh   = 2048 >> ii;
            theta_idx = ii * 2048 + (p >> logk) * hh + (p & ((1 << logk) - 1));
        } else {
            const int p    = ((b - 64) << 6) + p_loc;
            const int logk = 6 - ii;
            const int hh   = 32 >> ii;
            theta_idx = (ii + 6) * 2048 + (p >> logk) * hh + (p & ((1 << logk) - 1));
        }
        float s, c;
        sincosf(thetas[theta_idx], &s, &c);
        cs_c[ii][j] = c;
        cs_s[ii][j] = s;
    }

    // identity (overlaps with the sincos work above)
#pragma unroll
    for (int k = 0; k < 16; ++k) {
        const int e = tid + k * 256;
        sm[e >> 6][e & 63] = ((e >> 6) == (e & 63)) ? 1.0f : 0.0f;
    }
    __syncthreads();

    const int j = tid & 31;

#pragma unroll
    for (int ii = 0; ii < 6; ++ii) {
        const int half  = 32 >> ii;
        const int bm    = j >> (5 - ii);
        const int jm    = j & (half - 1);
        const int p_loc = (bm << (6 - ii)) + jm;
        const int q_loc = p_loc + half;
        const float c = cs_c[ii][j];
        const float s = cs_s[ii][j];
#pragma unroll
        for (int k = 0; k < 8; ++k) {
            const int row = (tid >> 5) + (k << 3);
            const float a  = sm[row][p_loc];
            const float bb = sm[row][q_loc];
            sm[row][p_loc] = c * a + s * bb;
            sm[row][q_loc] = c * bb - s * a;
        }
        __syncthreads();
    }

    if (is_head) {
#pragma unroll
        for (int k = 0; k < 16; ++k) {
            const int e  = tid + k * 256;
            const int rh = e >> 6;
            const int m  = e & 63;
            g_H[(b << 6) + (rh << 12) + m] = sm[rh][m];
        }
    } else {
        const int base = (b - 64) << 12;
#pragma unroll
        for (int k = 0; k < 16; ++k) {
            const int e = tid + k * 256;
            g_T[base + e] = sm[e >> 6][e & 63];
        }
    }
}

// ---------------------------------------------------------------------------
// Kernel 2: thread (r6, g, c4) loads t = That_B[r6, c&63] once, then writes
// rows r = r6 + 64*(8g + jr), jr = 0..7:
//   R[r, c..c+3] = g_H[r*64 + B] * t
// h loads batched upfront (MLP=8); row strides are compile-time constants
// (16 KB in g_H, 1 MB in out) -> immediate-offset LDG/STG.
// ---------------------------------------------------------------------------
__global__ __launch_bounds__(256) void outer_product_kernel(float4* __restrict__ out) {
    const int b   = blockIdx.x;                       // 0..2047
    const int c4  = ((b & 3) << 8) | threadIdx.x;     // 0..1023 (float4 within row)
    const int r6  = (b >> 2) & 63;
    const int g   = b >> 8;                           // 0..7
    const int c   = c4 << 2;
    const int B   = c >> 6;

    const int l = (B << 6) + r6;
    const float4 t = *reinterpret_cast<const float4*>(&g_T[(l << 6) + (c & 63)]);

    const int r0 = r6 + (g << 9);                     // rows r0 + 64*jr
    const float* __restrict__ hp = &g_H[(r0 << 6) + B];
    float h[8];
#pragma unroll
    for (int jr = 0; jr < 8; ++jr)
        h[jr] = hp[jr << 12];                         // +jr*4096 floats (16 KB)

    float4* __restrict__ o = out + (((long)r0 << 10) + c4);
#pragma unroll
    for (int jr = 0; jr < 8; ++jr) {
        const float hh = h[jr];
        o[(long)jr << 16] = make_float4(hh * t.x, hh * t.y, hh * t.z, hh * t.w);
    }
}

extern "C" void kernel_launch(void* const* d_in, const int* in_sizes, int n_in,
                              void* d_out, int out_size) {
    const float* thetas = (const float*)d_in[0];  // [12, 2048] fp32
    float4* out = (float4*)d_out;                 // [4096, 4096] fp32

    butterfly_mats_kernel<<<128, 256>>>(thetas);
    outer_product_kernel<<<2048, 256>>>(out);
}